// round 4
// baseline (speedup 1.0000x reference)
#include <cuda_runtime.h>
#include <stdint.h>

typedef unsigned long long u64;
typedef unsigned int u32;

// ---------------- constant-memory weights (uniform LDCU path) ----------------
__constant__ __align__(16) float cW1[64 * 64];  // [i][j], j contiguous
__constant__ __align__(16) float cW2[64 * 16];
__constant__ __align__(16) float cW3[16 * 8];
__constant__ __align__(16) float cW4[8 * 3];
__constant__ __align__(16) float cB1[64];
__constant__ __align__(16) float cB2[16];
__constant__ __align__(16) float cB3[8];
__constant__ __align__(16) float cB4[3];
__constant__ __align__(16) float cEnc[27];

// ---------------- helpers ----------------
static __device__ __forceinline__ u64 pack2(float lo, float hi) {
    u64 r; asm("mov.b64 %0, {%1, %2};" : "=l"(r) : "f"(lo), "f"(hi)); return r;
}
static __device__ __forceinline__ float2 unpack2(u64 v) {
    float2 f; asm("mov.b64 {%0, %1}, %2;" : "=f"(f.x), "=f"(f.y) : "l"(v)); return f;
}
static __device__ __forceinline__ void fma2(u64 &d, u64 a, u64 b) {
    asm("fma.rn.f32x2 %0, %1, %2, %0;" : "+l"(d) : "l"(a), "l"(b));
}
static __device__ __forceinline__ float leaky(float x) { return fmaxf(x, 0.01f * x); }
static __device__ __forceinline__ float sigmoidf(float x) { return 1.0f / (1.0f + __expf(-x)); }
static __device__ __forceinline__ float tanh_fast(float x) {
    return fmaf(2.0f, sigmoidf(2.0f * x), -1.0f);
}

// one feature scalar f against FC1 weight row (64 outs = 32 packed), uniform LDCU
static __device__ __forceinline__ void accum1(u64 *h1, const float *wrow, float f) {
    u64 fv = pack2(f, f);
    const ulonglong2 *w = (const ulonglong2 *)wrow;
#pragma unroll
    for (int q = 0; q < 16; q++) {
        ulonglong2 wq = w[q];
        fma2(h1[2 * q], fv, wq.x);
        fma2(h1[2 * q + 1], fv, wq.y);
    }
}

static __device__ __forceinline__ void encode(float i0, float i1, float &x, float &y) {
    float h[4];
#pragma unroll
    for (int j = 0; j < 4; j++)
        h[j] = tanh_fast(fmaf(i0, cEnc[j], fmaf(i1, cEnc[4 + j], cEnc[8 + j])));
    float z0 = cEnc[24], z1 = cEnc[25];
#pragma unroll
    for (int j = 0; j < 4; j++) {
        z0 = fmaf(h[j], cEnc[12 + j * 3 + 0], z0);
        z1 = fmaf(h[j], cEnc[12 + j * 3 + 1], z1);
    }
    x = sigmoidf(z0) * 255.0f;
    y = sigmoidf(z1) * 255.0f;
}

// FC3 (16->8) + FC4 (8->3) + sigmoid*255
static __device__ __forceinline__ float3 head(const float *a2) {
    u64 h3[4];
#pragma unroll
    for (int q = 0; q < 4; q++) h3[q] = pack2(cB3[2 * q], cB3[2 * q + 1]);
#pragma unroll
    for (int j = 0; j < 16; j++) {
        float a = a2[j];
        u64 av = pack2(a, a);
        const ulonglong2 *w = (const ulonglong2 *)(cW3 + j * 8);
#pragma unroll
        for (int q = 0; q < 2; q++) {
            ulonglong2 wq = w[q];
            fma2(h3[2 * q], av, wq.x);
            fma2(h3[2 * q + 1], av, wq.y);
        }
    }
    float o0 = cB4[0], o1 = cB4[1], o2 = cB4[2];
#pragma unroll
    for (int q = 0; q < 4; q++) {
        float2 v = unpack2(h3[q]);
        float a0 = leaky(v.x), a1 = leaky(v.y);
        int i0 = 2 * q, i1 = 2 * q + 1;
        o0 = fmaf(a0, cW4[i0 * 3 + 0], o0);
        o1 = fmaf(a0, cW4[i0 * 3 + 1], o1);
        o2 = fmaf(a0, cW4[i0 * 3 + 2], o2);
        o0 = fmaf(a1, cW4[i1 * 3 + 0], o0);
        o1 = fmaf(a1, cW4[i1 * 3 + 1], o1);
        o2 = fmaf(a1, cW4[i1 * 3 + 2], o2);
    }
    float3 r;
    r.x = sigmoidf(leaky(o0)) * 255.0f;
    r.y = sigmoidf(leaky(o1)) * 255.0f;
    r.z = sigmoidf(leaky(o2)) * 255.0f;
    return r;
}

#define SROW 36  // stage row stride in floats (144B: 16B-aligned, conflict-free phases)

// ---------------- kernel: cooperative gather, 1 point/thread ----------------
__global__ void __launch_bounds__(128) gridnet_coop(
    const float *__restrict__ pos, const float *__restrict__ dir,
    const float *__restrict__ pos_grid, const float *__restrict__ dir_grid,
    float *__restrict__ out, int n)
{
    __shared__ __align__(16) float stage[128 * SROW];  // 18KB: one corner-row per point
    __shared__ u32 aoff[128 * 8];                      // byte offsets of 8 corner rows per point

    const int tid = threadIdx.x;
    const int p = blockIdx.x * 128 + tid;
    const int pc = min(p, n - 1);

    // ---- encoders -> grid coords
    float gx[2], gy[2];
    {
        float a0 = pos[2 * pc], a1 = pos[2 * pc + 1];
        float e0 = dir[2 * pc], e1 = dir[2 * pc + 1];
        encode(a0, a1, gx[0], gy[0]);
        encode(e0, e1, gx[1], gy[1]);
    }

    // ---- corner offsets + blend weights
    float wts[8];
#pragma unroll
    for (int g = 0; g < 2; g++) {
        float x = gx[g], y = gy[g];
        int x0 = min((int)x, 255), y0 = min((int)y, 255);
        float xf = x - (float)x0, yf = y - (float)y0;
        int x1 = min(x0 + 1, 255), y1 = min(y0 + 1, 255);
        aoff[tid * 8 + g * 4 + 0] = (u32)(y0 * 256 + x0) * 128u;
        aoff[tid * 8 + g * 4 + 1] = (u32)(y0 * 256 + x1) * 128u;
        aoff[tid * 8 + g * 4 + 2] = (u32)(y1 * 256 + x0) * 128u;
        aoff[tid * 8 + g * 4 + 3] = (u32)(y1 * 256 + x1) * 128u;
        wts[g * 4 + 0] = (1.0f - xf) * (1.0f - yf);
        wts[g * 4 + 1] = xf * (1.0f - yf);
        wts[g * 4 + 2] = (1.0f - xf) * yf;
        wts[g * 4 + 3] = xf * yf;
    }

    // ---- FC1 accumulators (64 outs as 32 packed f32x2), init with bias
    u64 h1[32];
#pragma unroll
    for (int q = 0; q < 32; q++) h1[q] = pack2(cB1[2 * q], cB1[2 * q + 1]);

    const int group = tid >> 3, f = tid & 7;

    // ---- per grid: 4 cooperative corner chunks -> blend -> FC1 partial
#pragma unroll 1
    for (int g = 0; g < 2; g++) {
        const float *gbase = (g == 0) ? pos_grid : dir_grid;
        u64 feat[16];
#pragma unroll
        for (int q = 0; q < 16; q++) feat[q] = 0;

#pragma unroll 1
        for (int c = 0; c < 4; c++) {
            __syncthreads();  // stage/aoff reuse barrier
            // cooperative load: 128 rows, 8 lanes per row -> 4 lines per warp instr
#pragma unroll
            for (int i = 0; i < 8; i++) {
                int row = i * 16 + group;
                u32 off = aoff[row * 8 + g * 4 + c];
                float4 v = __ldg((const float4 *)((const char *)gbase + off) + f);
                *(float4 *)&stage[row * SROW + f * 4] = v;
            }
            __syncthreads();
            // blend own row into packed features
            float w = wts[g * 4 + c];
            u64 wv = pack2(w, w);
            const float4 *srow = (const float4 *)&stage[tid * SROW];
#pragma unroll
            for (int j = 0; j < 8; j++) {
                float4 v = srow[j];
                u64 v01 = pack2(v.x, v.y), v23 = pack2(v.z, v.w);
                fma2(feat[j * 2], wv, v01);
                fma2(feat[j * 2 + 1], wv, v23);
            }
        }

        // FC1 partial: this grid's 32 features
#pragma unroll
        for (int q = 0; q < 16; q++) {
            float2 fv = unpack2(feat[q]);
            accum1(h1, cW1 + (g * 32 + 2 * q) * 64, fv.x);
            accum1(h1, cW1 + (g * 32 + 2 * q + 1) * 64, fv.y);
        }
    }

    // ---- FC2: 64 -> 16
    u64 h2[8];
#pragma unroll
    for (int q = 0; q < 8; q++) h2[q] = pack2(cB2[2 * q], cB2[2 * q + 1]);
#pragma unroll
    for (int q = 0; q < 32; q++) {
        float2 v = unpack2(h1[q]);
        float a0 = leaky(v.x), a1 = leaky(v.y);
        u64 a0v = pack2(a0, a0), a1v = pack2(a1, a1);
        const ulonglong2 *w0 = (const ulonglong2 *)(cW2 + (2 * q) * 16);
        const ulonglong2 *w1 = (const ulonglong2 *)(cW2 + (2 * q + 1) * 16);
#pragma unroll
        for (int r = 0; r < 4; r++) {
            ulonglong2 wa = w0[r];
            fma2(h2[2 * r], a0v, wa.x);
            fma2(h2[2 * r + 1], a0v, wa.y);
            ulonglong2 wb = w1[r];
            fma2(h2[2 * r], a1v, wb.x);
            fma2(h2[2 * r + 1], a1v, wb.y);
        }
    }

    // ---- head
    float a2[16];
#pragma unroll
    for (int q = 0; q < 8; q++) {
        float2 v = unpack2(h2[q]);
        a2[2 * q] = leaky(v.x);
        a2[2 * q + 1] = leaky(v.y);
    }
    float3 o = head(a2);

    if (p < n) {
        out[p * 3 + 0] = o.x;
        out[p * 3 + 1] = o.y;
        out[p * 3 + 2] = o.z;
    }
}

extern "C" void kernel_launch(void *const *d_in, const int *in_sizes, int n_in,
                              void *d_out, int out_size)
{
    const float *pos = (const float *)d_in[0];
    const float *dir = (const float *)d_in[1];
    const float *pos_grid = (const float *)d_in[2];
    const float *dir_grid = (const float *)d_in[3];

    cudaMemcpyToSymbolAsync(cEnc, d_in[4], 8 * sizeof(float), 0, cudaMemcpyDeviceToDevice, 0);
    cudaMemcpyToSymbolAsync(cEnc, d_in[5], 4 * sizeof(float), 8 * sizeof(float), cudaMemcpyDeviceToDevice, 0);
    cudaMemcpyToSymbolAsync(cEnc, d_in[6], 12 * sizeof(float), 12 * sizeof(float), cudaMemcpyDeviceToDevice, 0);
    cudaMemcpyToSymbolAsync(cEnc, d_in[7], 3 * sizeof(float), 24 * sizeof(float), cudaMemcpyDeviceToDevice, 0);
    cudaMemcpyToSymbolAsync(cW1, d_in[8], 64 * 64 * sizeof(float), 0, cudaMemcpyDeviceToDevice, 0);
    cudaMemcpyToSymbolAsync(cB1, d_in[9], 64 * sizeof(float), 0, cudaMemcpyDeviceToDevice, 0);
    cudaMemcpyToSymbolAsync(cW2, d_in[10], 64 * 16 * sizeof(float), 0, cudaMemcpyDeviceToDevice, 0);
    cudaMemcpyToSymbolAsync(cB2, d_in[11], 16 * sizeof(float), 0, cudaMemcpyDeviceToDevice, 0);
    cudaMemcpyToSymbolAsync(cW3, d_in[12], 16 * 8 * sizeof(float), 0, cudaMemcpyDeviceToDevice, 0);
    cudaMemcpyToSymbolAsync(cB3, d_in[13], 8 * sizeof(float), 0, cudaMemcpyDeviceToDevice, 0);
    cudaMemcpyToSymbolAsync(cW4, d_in[14], 8 * 3 * sizeof(float), 0, cudaMemcpyDeviceToDevice, 0);
    cudaMemcpyToSymbolAsync(cB4, d_in[15], 3 * sizeof(float), 0, cudaMemcpyDeviceToDevice, 0);

    float *out = (float *)d_out;
    int n = in_sizes[0] / 2;
    int blocks = (n + 127) / 128;
    gridnet_coop<<<blocks, 128>>>(pos, dir, pos_grid, dir_grid, out, n);
}

// round 5
// speedup vs baseline: 2.4406x; 2.4406x over previous
#include <cuda_runtime.h>
#include <stdint.h>

typedef unsigned long long u64;
typedef unsigned int u32;

// ---------------- constant-memory weights (uniform LDCU path) ----------------
__constant__ __align__(16) float cW1[64 * 64];
__constant__ __align__(16) float cW2[64 * 16];
__constant__ __align__(16) float cW3[16 * 8];
__constant__ __align__(16) float cW4[8 * 3];
__constant__ __align__(16) float cB1[64];
__constant__ __align__(16) float cB2[16];
__constant__ __align__(16) float cB3[8];
__constant__ __align__(16) float cB4[3];
__constant__ __align__(16) float cEnc[27];

// ---------------- helpers ----------------
static __device__ __forceinline__ u64 pack2(float lo, float hi) {
    u64 r; asm("mov.b64 %0, {%1, %2};" : "=l"(r) : "f"(lo), "f"(hi)); return r;
}
static __device__ __forceinline__ float2 unpack2(u64 v) {
    float2 f; asm("mov.b64 {%0, %1}, %2;" : "=f"(f.x), "=f"(f.y) : "l"(v)); return f;
}
static __device__ __forceinline__ void fma2(u64 &d, u64 a, u64 b) {
    asm("fma.rn.f32x2 %0, %1, %2, %0;" : "+l"(d) : "l"(a), "l"(b));
}
static __device__ __forceinline__ float leaky(float x) { return fmaxf(x, 0.01f * x); }
static __device__ __forceinline__ float sigmoidf(float x) { return 1.0f / (1.0f + __expf(-x)); }
static __device__ __forceinline__ float tanh_fast(float x) {
    return fmaf(2.0f, sigmoidf(2.0f * x), -1.0f);
}

// one feature scalar against FC1 weight row (64 outs = 32 packed), uniform LDCU
static __device__ __forceinline__ void accum1(u64 *h1, const float *wrow, float f) {
    u64 fv = pack2(f, f);
    const ulonglong2 *w = (const ulonglong2 *)wrow;
#pragma unroll
    for (int q = 0; q < 16; q++) {
        ulonglong2 wq = w[q];
        fma2(h1[2 * q], fv, wq.x);
        fma2(h1[2 * q + 1], fv, wq.y);
    }
}

static __device__ __forceinline__ void encode(float i0, float i1, float &x, float &y) {
    float h[4];
#pragma unroll
    for (int j = 0; j < 4; j++)
        h[j] = tanh_fast(fmaf(i0, cEnc[j], fmaf(i1, cEnc[4 + j], cEnc[8 + j])));
    float z0 = cEnc[24], z1 = cEnc[25];
#pragma unroll
    for (int j = 0; j < 4; j++) {
        z0 = fmaf(h[j], cEnc[12 + j * 3 + 0], z0);
        z1 = fmaf(h[j], cEnc[12 + j * 3 + 1], z1);
    }
    x = sigmoidf(z0) * 255.0f;
    y = sigmoidf(z1) * 255.0f;
}

// FC3 (16->8) + FC4 (8->3) + sigmoid*255
static __device__ __forceinline__ float3 head(const float *a2) {
    u64 h3[4];
#pragma unroll
    for (int q = 0; q < 4; q++) h3[q] = pack2(cB3[2 * q], cB3[2 * q + 1]);
#pragma unroll
    for (int j = 0; j < 16; j++) {
        float a = a2[j];
        u64 av = pack2(a, a);
        const ulonglong2 *w = (const ulonglong2 *)(cW3 + j * 8);
#pragma unroll
        for (int q = 0; q < 2; q++) {
            ulonglong2 wq = w[q];
            fma2(h3[2 * q], av, wq.x);
            fma2(h3[2 * q + 1], av, wq.y);
        }
    }
    float o0 = cB4[0], o1 = cB4[1], o2 = cB4[2];
#pragma unroll
    for (int q = 0; q < 4; q++) {
        float2 v = unpack2(h3[q]);
        float a0 = leaky(v.x), a1 = leaky(v.y);
        int i0 = 2 * q, i1 = 2 * q + 1;
        o0 = fmaf(a0, cW4[i0 * 3 + 0], o0);
        o1 = fmaf(a0, cW4[i0 * 3 + 1], o1);
        o2 = fmaf(a0, cW4[i0 * 3 + 2], o2);
        o0 = fmaf(a1, cW4[i1 * 3 + 0], o0);
        o1 = fmaf(a1, cW4[i1 * 3 + 1], o1);
        o2 = fmaf(a1, cW4[i1 * 3 + 2], o2);
    }
    float3 r;
    r.x = sigmoidf(leaky(o0)) * 255.0f;
    r.y = sigmoidf(leaky(o1)) * 255.0f;
    r.z = sigmoidf(leaky(o2)) * 255.0f;
    return r;
}

// ---------------- kernel: warp-private cooperative gather ----------------
// stage[warp][row][slot], slot 0..15 = blended float4 feats (grid0: 0-7, grid1: 8-15),
// slot 16 = pad -> row stride 272B (68 floats) for conflict-bounded STS/LDS.
__global__ void __launch_bounds__(128) gridnet_warpcoop(
    const float *__restrict__ pos, const float *__restrict__ dir,
    const float *__restrict__ pos_grid, const float *__restrict__ dir_grid,
    float *__restrict__ out, int n)
{
    __shared__ __align__(16) float4 s_stage[4][32][17];   // 34816B
    __shared__ __align__(8) u64 s_meta[4][32][8];         // {off,w} per corner, 8192B

    const int tid = threadIdx.x;
    const int warp = tid >> 5, lane = tid & 31;
    const int grp = lane >> 3, f = lane & 7;
    const int p = blockIdx.x * 128 + tid;
    const int pc = min(p, n - 1);

    // ---- owner: encoders -> corner metadata (offset + blend weight) ----
    {
        float gx[2], gy[2];
        float a0 = pos[2 * pc], a1 = pos[2 * pc + 1];
        float e0 = dir[2 * pc], e1 = dir[2 * pc + 1];
        encode(a0, a1, gx[0], gy[0]);
        encode(e0, e1, gx[1], gy[1]);
#pragma unroll
        for (int g = 0; g < 2; g++) {
            float x = gx[g], y = gy[g];
            int x0 = min((int)x, 255), y0 = min((int)y, 255);
            float xf = x - (float)x0, yf = y - (float)y0;
            int x1 = min(x0 + 1, 255), y1 = min(y0 + 1, 255);
            u32 otl = (u32)(y0 * 256 + x0) * 128u;
            u32 otr = (u32)(y0 * 256 + x1) * 128u;
            u32 obl = (u32)(y1 * 256 + x0) * 128u;
            u32 obr = (u32)(y1 * 256 + x1) * 128u;
            float wtl = (1.0f - xf) * (1.0f - yf);
            float wtr = xf * (1.0f - yf);
            float wbl = (1.0f - xf) * yf;
            float wbr = xf * yf;
            s_meta[warp][lane][g * 4 + 0] = (u64)otl | ((u64)__float_as_uint(wtl) << 32);
            s_meta[warp][lane][g * 4 + 1] = (u64)otr | ((u64)__float_as_uint(wtr) << 32);
            s_meta[warp][lane][g * 4 + 2] = (u64)obl | ((u64)__float_as_uint(wbl) << 32);
            s_meta[warp][lane][g * 4 + 3] = (u64)obr | ((u64)__float_as_uint(wbr) << 32);
        }
    }
    __syncwarp();

    // ---- loader: 8 lanes per row, blend 4 corners in regs, store blended feats ----
    const float *gr0 = pos_grid, *gr1 = dir_grid;
#pragma unroll
    for (int i = 0; i < 8; i++) {
        int row = i * 4 + grp;
        const u64 *m = &s_meta[warp][row][0];
#pragma unroll
        for (int g = 0; g < 2; g++) {
            const float *gbase = (g == 0) ? gr0 : gr1;
            u64 acc01 = 0, acc23 = 0;
#pragma unroll
            for (int c = 0; c < 4; c++) {
                u64 mw = m[g * 4 + c];                 // broadcast LDS.64 (8 lanes same addr)
                u32 off = (u32)mw;
                float w = __uint_as_float((u32)(mw >> 32));
                float4 v = __ldg((const float4 *)((const char *)gbase + off) + f);
                u64 wv = pack2(w, w);
                fma2(acc01, wv, pack2(v.x, v.y));
                fma2(acc23, wv, pack2(v.z, v.w));
            }
            float2 lo = unpack2(acc01), hi = unpack2(acc23);
            s_stage[warp][row][g * 8 + f] = make_float4(lo.x, lo.y, hi.x, hi.y);
        }
    }
    __syncwarp();

    // ---- owner: FC1 streamed from staged feats (slot j float k -> W1 row 4j+k) ----
    u64 h1[32];
#pragma unroll
    for (int q = 0; q < 32; q++) h1[q] = pack2(cB1[2 * q], cB1[2 * q + 1]);

#pragma unroll
    for (int j = 0; j < 16; j++) {
        float4 v = s_stage[warp][lane][j];
        accum1(h1, cW1 + (4 * j + 0) * 64, v.x);
        accum1(h1, cW1 + (4 * j + 1) * 64, v.y);
        accum1(h1, cW1 + (4 * j + 2) * 64, v.z);
        accum1(h1, cW1 + (4 * j + 3) * 64, v.w);
    }

    // ---- FC2: 64 -> 16 ----
    u64 h2[8];
#pragma unroll
    for (int q = 0; q < 8; q++) h2[q] = pack2(cB2[2 * q], cB2[2 * q + 1]);
#pragma unroll
    for (int q = 0; q < 32; q++) {
        float2 v = unpack2(h1[q]);
        float a0 = leaky(v.x), a1 = leaky(v.y);
        u64 a0v = pack2(a0, a0), a1v = pack2(a1, a1);
        const ulonglong2 *w0 = (const ulonglong2 *)(cW2 + (2 * q) * 16);
        const ulonglong2 *w1 = (const ulonglong2 *)(cW2 + (2 * q + 1) * 16);
#pragma unroll
        for (int r = 0; r < 4; r++) {
            ulonglong2 wa = w0[r];
            fma2(h2[2 * r], a0v, wa.x);
            fma2(h2[2 * r + 1], a0v, wa.y);
            ulonglong2 wb = w1[r];
            fma2(h2[2 * r], a1v, wb.x);
            fma2(h2[2 * r + 1], a1v, wb.y);
        }
    }

    // ---- head ----
    float a2[16];
#pragma unroll
    for (int q = 0; q < 8; q++) {
        float2 v = unpack2(h2[q]);
        a2[2 * q] = leaky(v.x);
        a2[2 * q + 1] = leaky(v.y);
    }
    float3 o = head(a2);

    if (p < n) {
        out[p * 3 + 0] = o.x;
        out[p * 3 + 1] = o.y;
        out[p * 3 + 2] = o.z;
    }
}

extern "C" void kernel_launch(void *const *d_in, const int *in_sizes, int n_in,
                              void *d_out, int out_size)
{
    const float *pos = (const float *)d_in[0];
    const float *dir = (const float *)d_in[1];
    const float *pos_grid = (const float *)d_in[2];
    const float *dir_grid = (const float *)d_in[3];

    cudaMemcpyToSymbolAsync(cEnc, d_in[4], 8 * sizeof(float), 0, cudaMemcpyDeviceToDevice, 0);
    cudaMemcpyToSymbolAsync(cEnc, d_in[5], 4 * sizeof(float), 8 * sizeof(float), cudaMemcpyDeviceToDevice, 0);
    cudaMemcpyToSymbolAsync(cEnc, d_in[6], 12 * sizeof(float), 12 * sizeof(float), cudaMemcpyDeviceToDevice, 0);
    cudaMemcpyToSymbolAsync(cEnc, d_in[7], 3 * sizeof(float), 24 * sizeof(float), cudaMemcpyDeviceToDevice, 0);
    cudaMemcpyToSymbolAsync(cW1, d_in[8], 64 * 64 * sizeof(float), 0, cudaMemcpyDeviceToDevice, 0);
    cudaMemcpyToSymbolAsync(cB1, d_in[9], 64 * sizeof(float), 0, cudaMemcpyDeviceToDevice, 0);
    cudaMemcpyToSymbolAsync(cW2, d_in[10], 64 * 16 * sizeof(float), 0, cudaMemcpyDeviceToDevice, 0);
    cudaMemcpyToSymbolAsync(cB2, d_in[11], 16 * sizeof(float), 0, cudaMemcpyDeviceToDevice, 0);
    cudaMemcpyToSymbolAsync(cW3, d_in[12], 16 * 8 * sizeof(float), 0, cudaMemcpyDeviceToDevice, 0);
    cudaMemcpyToSymbolAsync(cB3, d_in[13], 8 * sizeof(float), 0, cudaMemcpyDeviceToDevice, 0);
    cudaMemcpyToSymbolAsync(cW4, d_in[14], 8 * 3 * sizeof(float), 0, cudaMemcpyDeviceToDevice, 0);
    cudaMemcpyToSymbolAsync(cB4, d_in[15], 3 * sizeof(float), 0, cudaMemcpyDeviceToDevice, 0);

    float *out = (float *)d_out;
    int n = in_sizes[0] / 2;
    int blocks = (n + 127) / 128;
    gridnet_warpcoop<<<blocks, 128>>>(pos, dir, pos_grid, dir_grid, out, n);
}